// round 6
// baseline (speedup 1.0000x reference)
#include <cuda_runtime.h>
#include <cstdint>

#define BB 256
#define CC 2048
#define HWN 49
#define KK 16
typedef unsigned long long ull;

// Static device scratch
__device__ __align__(16) float g_part[BB * 8 * 784];  // [b][q][k*49+hw]
__device__ __align__(16) float g_fc16[BB * 784];      // [b][hw*16+k], BN'd, /49
__device__ __align__(16) float g_wT[CC * KK];         // [c][16]
__device__ float g_binv[KK], g_boff[KK];

__device__ __forceinline__ ull ffma2(ull a, ull b, ull c) {
    ull d;
    asm("fma.rn.f32x2 %0, %1, %2, %3;" : "=l"(d) : "l"(a), "l"(b), "l"(c));
    return d;
}
__device__ __forceinline__ ull pack2(float x, float y) {
    ull r;
    asm("mov.b64 %0, {%1, %2};" : "=l"(r) : "f"(x), "f"(y));
    return r;
}
__device__ __forceinline__ void unpack2(ull v, float& x, float& y) {
    asm("mov.b64 {%0, %1}, %2;" : "=f"(x), "=f"(y) : "l"(v));
}

// ============================================================================
// K0: transpose weights -> g_wT[c][16]; BN constants (1/49 folded)
// ============================================================================
__global__ void k0_prep(const float* __restrict__ w16,
                        const float* __restrict__ bng, const float* __restrict__ bnb,
                        const float* __restrict__ bnm, const float* __restrict__ bnv) {
    int idx = blockIdx.x * 256 + threadIdx.x;
    if (idx < CC * KK) {
        int c = idx >> 4, k = idx & 15;
        g_wT[idx] = w16[k * CC + c];
    }
    if (blockIdx.x == 0 && threadIdx.x < KK) {
        int k = threadIdx.x;
        float iv = bng[k] * rsqrtf(bnv[k] + 1e-5f);
        g_binv[k] = iv * (1.0f / 49.0f);
        g_boff[k] = (bnb[k] - bnm[k] * iv) * (1.0f / 49.0f);
    }
}

// ============================================================================
// K1: partial conv. Block = (c-slice q of 256, b), 128 threads (4 warps x 64c).
// Lanes = hw. Double-buffered chunks of 8 c: 16 LDGs in flight per warp
// (MLP ~16) hides DRAM latency; weights via uniform L1-hit LDG.128.
// ============================================================================
__global__ __launch_bounds__(128) void k1_conv(const float* __restrict__ fm) {
    __shared__ float red[4 * 784];
    const int b = blockIdx.y, q = blockIdx.x;
    const int tid = threadIdx.x;
    const int lane = tid & 31, wid = tid >> 5;
    const bool hi = (lane < 17);

    const float* fmc = fm + (size_t)b * (CC * HWN) + (size_t)(q * 256 + wid * 64) * HWN;
    const float* wq = g_wT + (q * 256 + wid * 64) * KK;

    ull acc0[8], acc1[8];
#pragma unroll
    for (int i = 0; i < 8; i++) { acc0[i] = 0ull; acc1[i] = 0ull; }

    float v0[2][8], v1[2][8];

    // prologue: chunk 0
#pragma unroll
    for (int j = 0; j < 8; j++) {
        v0[0][j] = fmc[j * HWN + lane];
        v1[0][j] = hi ? fmc[j * HWN + lane + 32] : 0.0f;
    }

#pragma unroll
    for (int ch = 0; ch < 8; ch++) {
        const int cur = ch & 1, nxt = cur ^ 1;
        if (ch < 7) {
            const float* fmn = fmc + (ch + 1) * 8 * HWN;
#pragma unroll
            for (int j = 0; j < 8; j++) {
                v0[nxt][j] = fmn[j * HWN + lane];
                v1[nxt][j] = hi ? fmn[j * HWN + lane + 32] : 0.0f;
            }
        }
#pragma unroll
        for (int j = 0; j < 8; j++) {
            const int c = ch * 8 + j;
            const ulonglong2* wp = (const ulonglong2*)(wq + c * KK);
            ulonglong2 wA = wp[0], wB = wp[1], wC = wp[2], wD = wp[3];
            ull vv0 = pack2(v0[cur][j], v0[cur][j]);
            ull vv1 = pack2(v1[cur][j], v1[cur][j]);
            acc0[0] = ffma2(wA.x, vv0, acc0[0]);  acc1[0] = ffma2(wA.x, vv1, acc1[0]);
            acc0[1] = ffma2(wA.y, vv0, acc0[1]);  acc1[1] = ffma2(wA.y, vv1, acc1[1]);
            acc0[2] = ffma2(wB.x, vv0, acc0[2]);  acc1[2] = ffma2(wB.x, vv1, acc1[2]);
            acc0[3] = ffma2(wB.y, vv0, acc0[3]);  acc1[3] = ffma2(wB.y, vv1, acc1[3]);
            acc0[4] = ffma2(wC.x, vv0, acc0[4]);  acc1[4] = ffma2(wC.x, vv1, acc1[4]);
            ac0:    ;
            acc0[5] = ffma2(wC.y, vv0, acc0[5]);  acc1[5] = ffma2(wC.y, vv1, acc1[5]);
            acc0[6] = ffma2(wD.x, vv0, acc0[6]);  acc1[6] = ffma2(wD.x, vv1, acc1[6]);
            acc0[7] = ffma2(wD.y, vv0, acc0[7]);  acc1[7] = ffma2(wD.y, vv1, acc1[7]);
        }
    }

    // per-warp partials -> smem
#pragma unroll
    for (int kp = 0; kp < 8; kp++) {
        float a, c0;
        unpack2(acc0[kp], a, c0);
        red[wid * 784 + (2 * kp) * 49 + lane] = a;
        red[wid * 784 + (2 * kp + 1) * 49 + lane] = c0;
        if (hi) {
            float x, y;
            unpack2(acc1[kp], x, y);
            red[wid * 784 + (2 * kp) * 49 + lane + 32] = x;
            red[wid * 784 + (2 * kp + 1) * 49 + lane + 32] = y;
        }
    }
    __syncthreads();

    float* dst = g_part + ((size_t)b * 8 + q) * 784;
    for (int o = tid; o < 784; o += 128) {
        float s = (red[o] + red[784 + o]) + (red[2 * 784 + o] + red[3 * 784 + o]);
        dst[o] = s;
    }
}

// ============================================================================
// K1b: reduce 8 c-slices, apply BN, relayout [k*49+hw] -> [hw*16+k]
// ============================================================================
__global__ __launch_bounds__(784) void k1b_reduce() {
    const int b = blockIdx.x;
    const int o = threadIdx.x;
    const float* src = g_part + (size_t)b * 8 * 784;
    float s = 0.0f;
#pragma unroll
    for (int qq = 0; qq < 8; qq++) s += src[qq * 784 + o];
    int k = o / 49;
    int hw = o - k * 49;
    g_fc16[b * 784 + hw * 16 + k] = s * g_binv[k] + g_boff[k];
}

// ============================================================================
// K2: bilinear, hw-outer / c-inner. Block = (c-tile 512, b), 128 threads,
// 4 c/thread (accs persist in regs). Per hw: 4 uniform LDG.128 fcs (pipelined
// one hw ahead, L1-hit) + 4 conflict-free LDS.32 + 64 FFMA2  -> FMA-bound.
// ============================================================================
__global__ __launch_bounds__(128) void k2_bilinear(const float* __restrict__ fm,
                                                   float* __restrict__ out) {
    extern __shared__ float fms[];  // 512*49 floats = 100352 B

    const int tid = threadIdx.x;
    const int b = blockIdx.y;
    const int cbase = blockIdx.x * 512;

    // stage featmap tile (contiguous float4)
    const float* fmb = fm + (size_t)b * (CC * HWN) + (size_t)cbase * HWN;
    for (int i = tid; i < (512 * HWN) / 4; i += 128)
        ((float4*)fms)[i] = ((const float4*)fmb)[i];
    __syncthreads();

    const float* r0 = &fms[tid * HWN];
    const float* r1 = &fms[(tid + 128) * HWN];
    const float* r2 = &fms[(tid + 256) * HWN];
    const float* r3 = &fms[(tid + 384) * HWN];
    const ulonglong2* fcb = (const ulonglong2*)(g_fc16 + b * 784);

    ull acc[4][8];
#pragma unroll
    for (int i = 0; i < 4; i++)
#pragma unroll
        for (int j = 0; j < 8; j++) acc[i][j] = 0ull;

    // pipeline: fcs quads for hw=0
    ulonglong2 q0 = fcb[0], q1 = fcb[1], q2 = fcb[2], q3 = fcb[3];

#pragma unroll 7
    for (int hw = 0; hw < HWN; hw++) {
        ulonglong2 n0, n1, n2, n3;
        if (hw < HWN - 1) {
            n0 = fcb[(hw + 1) * 4 + 0];
            n1 = fcb[(hw + 1) * 4 + 1];
            n2 = fcb[(hw + 1) * 4 + 2];
            n3 = fcb[(hw + 1) * 4 + 3];
        }
        float va = r0[hw], vb = r1[hw], vc = r2[hw], vd = r3[hw];
        ull vva = pack2(va, va), vvb = pack2(vb, vb);
        ull vvc = pack2(vc, vc), vvd = pack2(vd, vd);

        acc[0][0] = ffma2(q0.x, vva, acc[0][0]);  acc[1][0] = ffma2(q0.x, vvb, acc[1][0]);
        acc[2][0] = ffma2(q0.x, vvc, acc[2][0]);  acc[3][0] = ffma2(q0.x, vvd, acc[3][0]);
        acc[0][1] = ffma2(q0.y, vva, acc[0][1]);  acc[1][1] = ffma2(q0.y, vvb, acc[1][1]);
        acc[2][1] = ffma2(q0.y, vvc, acc[2][1]);  acc[3][1] = ffma2(q0.y, vvd, acc[3][1]);
        acc[0][2] = ffma2(q1.x, vva, acc[0][2]);  acc[1][2] = ffma2(q1.x, vvb, acc[1][2]);
        acc[2][2] = ffma2(q1.x, vvc, acc[2][2]);  acc[3][2] = ffma2(q1.x, vvd, acc[3][2]);
        acc[0][3] = ffma2(q1.y, vva, acc[0][3]);  acc[1][3] = ffma2(q1.y, vvb, acc[1][3]);
        acc[2][3] = ffma2(q1.y, vvc, acc[2][3]);  acc[3][3] = ffma2(q1.y, vvd, acc[3][3]);
        acc[0][4] = ffma2(q2.x, vva, acc[0][4]);  acc[1][4] = ffma2(q2.x, vvb, acc[1][4]);
        acc[2][4] = ffma2(q2.x, vvc, acc[2][4]);  acc[3][4] = ffma2(q2.x, vvd, acc[3][4]);
        acc[0][5] = ffma2(q2.y, vva, acc[0][5]);  acc[1][5] = ffma2(q2.y, vvb, acc[1][5]);
        acc[2][5] = ffma2(q2.y, vvc, acc[2][5]);  acc[3][5] = ffma2(q2.y, vvd, acc[3][5]);
        acc[0][6] = ffma2(q3.x, vva, acc[0][6]);  acc[1][6] = ffma2(q3.x, vvb, acc[1][6]);
        acc[2][6] = ffma2(q3.x, vvc, acc[2][6]);  acc[3][6] = ffma2(q3.x, vvd, acc[3][6]);
        acc[0][7] = ffma2(q3.y, vva, acc[0][7]);  acc[1][7] = ffma2(q3.y, vvb, acc[1][7]);
        acc[2][7] = ffma2(q3.y, vvc, acc[2][7]);  acc[3][7] = ffma2(q3.y, vvd, acc[3][7]);

        q0 = n0; q1 = n1; q2 = n2; q3 = n3;
    }

#pragma unroll
    for (int i = 0; i < 4; i++) {
        float* ob = out + (size_t)b * 32768 + cbase + i * 128 + tid;
#pragma unroll
        for (int kp = 0; kp < 8; kp++) {
            float x, y;
            unpack2(acc[i][kp], x, y);
            ob[(2 * kp) * 2048] = x;
            ob[(2 * kp + 1) * 2048] = y;
        }
    }
}

extern "C" void kernel_launch(void* const* d_in, const int* in_sizes, int n_in,
                              void* d_out, int out_size) {
    const float* fm  = (const float*)d_in[0];  // [256,2048,7,7]
    const float* w16 = (const float*)d_in[1];  // [16,2048]
    const float* bng = (const float*)d_in[2];
    const float* bnb = (const float*)d_in[3];
    const float* bnm = (const float*)d_in[4];
    const float* bnv = (const float*)d_in[5];
    float* out = (float*)d_out;

    cudaFuncSetAttribute(k2_bilinear, cudaFuncAttributeMaxDynamicSharedMemorySize,
                         512 * HWN * (int)sizeof(float));

    k0_prep<<<(CC * KK + 255) / 256, 256>>>(w16, bng, bnb, bnm, bnv);
    dim3 g1(8, BB);
    k1_conv<<<g1, 128>>>(fm);
    k1b_reduce<<<BB, 784>>>();
    dim3 g2(4, BB);
    k2_bilinear<<<g2, 128, 512 * HWN * (int)sizeof(float)>>>(fm, out);
}

// round 9
// speedup vs baseline: 1.1842x; 1.1842x over previous
#include <cuda_runtime.h>
#include <cstdint>

#define BB 256
#define CC 2048
#define HWN 49
#define KK 16
typedef unsigned long long ull;

// Static device scratch
__device__ __align__(16) float g_part[BB * 8 * 784];  // [b][q][k*49+hw]
__device__ __align__(16) float g_fc16[BB * 784];      // [b][hw*16+k], BN'd, /49
__device__ __align__(16) float g_wT[CC * KK];         // [c][16]
__device__ float g_binv[KK], g_boff[KK];

__device__ __forceinline__ ull ffma2(ull a, ull b, ull c) {
    ull d;
    asm("fma.rn.f32x2 %0, %1, %2, %3;" : "=l"(d) : "l"(a), "l"(b), "l"(c));
    return d;
}
__device__ __forceinline__ ull pack2(float x, float y) {
    ull r;
    asm("mov.b64 %0, {%1, %2};" : "=l"(r) : "f"(x), "f"(y));
    return r;
}
__device__ __forceinline__ void unpack2(ull v, float& x, float& y) {
    asm("mov.b64 {%0, %1}, %2;" : "=f"(x), "=f"(y) : "l"(v));
}

// ============================================================================
// K0: transpose weights -> g_wT[c][16]; BN constants (1/49 folded)
// ============================================================================
__global__ void k0_prep(const float* __restrict__ w16,
                        const float* __restrict__ bng, const float* __restrict__ bnb,
                        const float* __restrict__ bnm, const float* __restrict__ bnv) {
    int idx = blockIdx.x * 256 + threadIdx.x;
    if (idx < CC * KK) {
        int c = idx >> 4, k = idx & 15;
        g_wT[idx] = w16[k * CC + c];
    }
    if (blockIdx.x == 0 && threadIdx.x < KK) {
        int k = threadIdx.x;
        float iv = bng[k] * rsqrtf(bnv[k] + 1e-5f);
        g_binv[k] = iv * (1.0f / 49.0f);
        g_boff[k] = (bnb[k] - bnm[k] * iv) * (1.0f / 49.0f);
    }
}

// ============================================================================
// K1: partial conv. Block = (c-slice q of 256, b), 256 threads (8 warps x 32c).
// Lanes = hw. Depth-2 ring prefetch on featmap only (low reg pressure);
// weights via uniform L1-resident LDG.128. ~65 regs -> no spills,
// 4+ blocks/SM -> 32+ warps to cover DRAM latency.
// ============================================================================
__global__ __launch_bounds__(256) void k1_conv(const float* __restrict__ fm) {
    __shared__ float red[8 * 784];
    const int b = blockIdx.y, q = blockIdx.x;
    const int tid = threadIdx.x;
    const int lane = tid & 31, wid = tid >> 5;
    const bool hi = (lane < 17);

    const float* fmc = fm + (size_t)b * (CC * HWN) + (size_t)(q * 256 + wid * 32) * HWN;
    const float* wq = g_wT + (q * 256 + wid * 32) * KK;

    ull acc0[8], acc1[8];
#pragma unroll
    for (int i = 0; i < 8; i++) { acc0[i] = 0ull; acc1[i] = 0ull; }

    // depth-2 ring on featmap values
    float a0[2], a1[2];
    a0[0] = fmc[lane];
    a1[0] = hi ? fmc[lane + 32] : 0.0f;
    a0[1] = fmc[HWN + lane];
    a1[1] = hi ? fmc[HWN + lane + 32] : 0.0f;

#pragma unroll 8
    for (int j = 0; j < 32; j++) {
        const int slot = j & 1;
        float v0 = a0[slot], v1 = a1[slot];
        if (j < 30) {
            a0[slot] = fmc[(j + 2) * HWN + lane];
            a1[slot] = hi ? fmc[(j + 2) * HWN + lane + 32] : 0.0f;
        }
        const ulonglong2* wp = (const ulonglong2*)(wq + j * KK);
        ulonglong2 wA = wp[0], wB = wp[1], wC = wp[2], wD = wp[3];
        ull vv0 = pack2(v0, v0), vv1 = pack2(v1, v1);
        acc0[0] = ffma2(wA.x, vv0, acc0[0]);  acc1[0] = ffma2(wA.x, vv1, acc1[0]);
        acc0[1] = ffma2(wA.y, vv0, acc0[1]);  acc1[1] = ffma2(wA.y, vv1, acc1[1]);
        acc0[2] = ffma2(wB.x, vv0, acc0[2]);  acc1[2] = ffma2(wB.x, vv1, acc1[2]);
        acc0[3] = ffma2(wB.y, vv0, acc0[3]);  acc1[3] = ffma2(wB.y, vv1, acc1[3]);
        acc0[4] = ffma2(wC.x, vv0, acc0[4]);  acc1[4] = ffma2(wC.x, vv1, acc1[4]);
        acc0[5] = ffma2(wC.y, vv0, acc0[5]);  acc1[5] = ffma2(wC.y, vv1, acc1[5]);
        acc0[6] = ffma2(wD.x, vv0, acc0[6]);  acc1[6] = ffma2(wD.x, vv1, acc1[6]);
        acc0[7] = ffma2(wD.y, vv0, acc0[7]);  acc1[7] = ffma2(wD.y, vv1, acc1[7]);
    }

    // per-warp partials -> smem
#pragma unroll
    for (int kp = 0; kp < 8; kp++) {
        float a, c0;
        unpack2(acc0[kp], a, c0);
        red[wid * 784 + (2 * kp) * 49 + lane] = a;
        red[wid * 784 + (2 * kp + 1) * 49 + lane] = c0;
        if (hi) {
            float x, y;
            unpack2(acc1[kp], x, y);
            red[wid * 784 + (2 * kp) * 49 + lane + 32] = x;
            red[wid * 784 + (2 * kp + 1) * 49 + lane + 32] = y;
        }
    }
    __syncthreads();

    float* dst = g_part + ((size_t)b * 8 + q) * 784;
    for (int o = tid; o < 784; o += 256) {
        float s = 0.0f;
#pragma unroll
        for (int w = 0; w < 8; w++) s += red[w * 784 + o];
        dst[o] = s;
    }
}

// ============================================================================
// K1b: reduce 8 c-slices, apply BN, relayout [k*49+hw] -> [hw*16+k]
// ============================================================================
__global__ __launch_bounds__(784) void k1b_reduce() {
    const int b = blockIdx.x;
    const int o = threadIdx.x;
    const float* src = g_part + (size_t)b * 8 * 784;
    float s = 0.0f;
#pragma unroll
    for (int qq = 0; qq < 8; qq++) s += src[qq * 784 + o];
    int k = o / 49;
    int hw = o - k * 49;
    g_fc16[b * 784 + hw * 16 + k] = s * g_binv[k] + g_boff[k];
}

// ============================================================================
// K2: bilinear. Block = (c-tile 256, b), 128 threads, 2 c/thread.
// featmap tile (50KB dyn smem) + fc16 tile (3KB) in shared; fc quads via
// LDS.128 (29-cyc, trivially hidden); 22 inst per 16 FFMA2.
// 53KB/block -> 4 blocks/SM = 16 warps.
// ============================================================================
__global__ __launch_bounds__(128) void k2_bilinear(const float* __restrict__ fm,
                                                   float* __restrict__ out) {
    extern __shared__ float fms[];                // 256*49 = 12544 floats, 50176B
    __shared__ __align__(16) float fcs[784];      // [hw][16]

    const int tid = threadIdx.x;
    const int b = blockIdx.y;
    const int cbase = blockIdx.x * 256;

    // stage fc16 (already [hw][16])
    for (int i = tid; i < 784; i += 128) fcs[i] = g_fc16[b * 784 + i];
    // stage featmap tile (contiguous float4, 3136 float4s)
    const float* fmb = fm + (size_t)b * (CC * HWN) + (size_t)cbase * HWN;
    for (int i = tid; i < (256 * HWN) / 4; i += 128)
        ((float4*)fms)[i] = ((const float4*)fmb)[i];
    __syncthreads();

    const float* rA = &fms[tid * HWN];
    const float* rB = &fms[(tid + 128) * HWN];
    const ulonglong2* fq = (const ulonglong2*)fcs;

    ull accA[8], accB[8];
#pragma unroll
    for (int i = 0; i < 8; i++) { accA[i] = 0ull; accB[i] = 0ull; }

#pragma unroll 7
    for (int hw = 0; hw < HWN; hw++) {
        ulonglong2 q0 = fq[hw * 4 + 0];   // LDS.128: k 0..3
        ulonglong2 q1 = fq[hw * 4 + 1];   // k 4..7
        ulonglong2 q2 = fq[hw * 4 + 2];   // k 8..11
        ulonglong2 q3 = fq[hw * 4 + 3];   // k 12..15
        float va = rA[hw], vb = rB[hw];   // conflict-free LDS.32 (49 odd)
        ull vva = pack2(va, va), vvb = pack2(vb, vb);
        accA[0] = ffma2(q0.x, vva, accA[0]);  accB[0] = ffma2(q0.x, vvb, accB[0]);
        accA[1] = ffma2(q0.y, vva, accA[1]);  accB[1] = ffma2(q0.y, vvb, accB[1]);
        accA[2] = ffma2(q1.x, vva, accA[2]);  accB[2] = ffma2(q1.x, vvb, accB[2]);
        accA[3] = ffma2(q1.y, vva, accA[3]);  accB[3] = ffma2(q1.y, vvb, accB[3]);
        accA[4] = ffma2(q2.x, vva, accA[4]);  accB[4] = ffma2(q2.x, vvb, accB[4]);
        accA[5] = ffma2(q2.y, vva, accA[5]);  accB[5] = ffma2(q2.y, vvb, accB[5]);
        accA[6] = ffma2(q3.x, vva, accA[6]);  accB[6] = ffma2(q3.x, vvb, accB[6]);
        accA[7] = ffma2(q3.y, vva, accA[7]);  accB[7] = ffma2(q3.y, vvb, accB[7]);
    }

    float* obA = out + (size_t)b * 32768 + cbase + tid;
    float* obB = obA + 128;
#pragma unroll
    for (int kp = 0; kp < 8; kp++) {
        float x, y;
        unpack2(accA[kp], x, y);
        obA[(2 * kp) * 2048] = x;
        obA[(2 * kp + 1) * 2048] = y;
        unpack2(accB[kp], x, y);
        obB[(2 * kp) * 2048] = x;
        obB[(2 * kp + 1) * 2048] = y;
    }
}

extern "C" void kernel_launch(void* const* d_in, const int* in_sizes, int n_in,
                              void* d_out, int out_size) {
    const float* fm  = (const float*)d_in[0];  // [256,2048,7,7]
    const float* w16 = (const float*)d_in[1];  // [16,2048]
    const float* bng = (const float*)d_in[2];
    const float* bnb = (const float*)d_in[3];
    const float* bnm = (const float*)d_in[4];
    const float* bnv = (const float*)d_in[5];
    float* out = (float*)d_out;

    const int k2_smem = 256 * HWN * (int)sizeof(float);  // 50176 B
    cudaFuncSetAttribute(k2_bilinear, cudaFuncAttributeMaxDynamicSharedMemorySize,
                         k2_smem);

    k0_prep<<<(CC * KK + 255) / 256, 256>>>(w16, bng, bnb, bnm, bnv);
    dim3 g1(8, BB);
    k1_conv<<<g1, 256>>>(fm);
    k1b_reduce<<<BB, 784>>>();
    dim3 g2(8, BB);   // 2048 blocks: (c-tile of 256, b)
    k2_bilinear<<<g2, 128, k2_smem>>>(fm, out);
}

// round 10
// speedup vs baseline: 2.2570x; 1.9060x over previous
#include <cuda_runtime.h>
#include <cstdint>

#define BB 256
#define CC 2048
#define HWN 49
#define KK 16
typedef unsigned long long ull;

// Static device scratch
__device__ __align__(16) float g_part[BB * 8 * 784];  // [b][q][k*49+hw]
__device__ __align__(16) float g_fc16[BB * 784];      // [b][hw*16+k], BN'd, /49
__device__ __align__(16) float g_wT[CC * KK];         // [c][16]
__device__ float g_binv[KK], g_boff[KK];

__device__ __forceinline__ ull ffma2(ull a, ull b, ull c) {
    ull d;
    asm("fma.rn.f32x2 %0, %1, %2, %3;" : "=l"(d) : "l"(a), "l"(b), "l"(c));
    return d;
}
__device__ __forceinline__ ull pack2(float x, float y) {
    ull r;
    asm("mov.b64 %0, {%1, %2};" : "=l"(r) : "f"(x), "f"(y));
    return r;
}
__device__ __forceinline__ void unpack2(ull v, float& x, float& y) {
    asm("mov.b64 {%0, %1}, %2;" : "=f"(x), "=f"(y) : "l"(v));
}
__device__ __forceinline__ uint32_t smem_u32(const void* p) {
    uint32_t a;
    asm("{ .reg .u64 t; cvta.to.shared.u64 t, %1; cvt.u32.u64 %0, t; }"
        : "=r"(a) : "l"(p));
    return a;
}

// ============================================================================
// K0: transpose weights -> g_wT[c][16]; BN constants (1/49 folded)
// ============================================================================
__global__ void k0_prep(const float* __restrict__ w16,
                        const float* __restrict__ bng, const float* __restrict__ bnb,
                        const float* __restrict__ bnm, const float* __restrict__ bnv) {
    int idx = blockIdx.x * 256 + threadIdx.x;
    if (idx < CC * KK) {
        int c = idx >> 4, k = idx & 15;
        g_wT[idx] = w16[k * CC + c];
    }
    if (blockIdx.x == 0 && threadIdx.x < KK) {
        int k = threadIdx.x;
        float iv = bng[k] * rsqrtf(bnv[k] + 1e-5f);
        g_binv[k] = iv * (1.0f / 49.0f);
        g_boff[k] = (bnb[k] - bnm[k] * iv) * (1.0f / 49.0f);
    }
}

// ============================================================================
// K1: partial conv with b-PAIRING (G=2). Block = (q-slice of 256 c, b-pair).
// 256 thr, 8 warps x 32 c. Weight quads (uniform, replicated on the return
// bus) fetched ONCE per warp-c and amortized over 2 batches x 2 hw-halves
// = 32 FFMA2. Weights staged in smem (29-cyc LDS); fm depth-1 ring.
// ============================================================================
__global__ __launch_bounds__(256, 2) void k1_conv(const float* __restrict__ fm) {
    __shared__ __align__(16) float wts[256 * 16];  // [c_local][16], 16KB
    __shared__ float red[8 * 784];                 // 25KB (reused for b0 then b1)

    const int bp = blockIdx.y, q = blockIdx.x;
    const int b0 = bp * 2, b1 = b0 + 1;
    const int tid = threadIdx.x;
    const int lane = tid & 31, wid = tid >> 5;
    const bool hi = (lane < 17);

    // stage weight slice (contiguous float4)
    {
        const float4* src = (const float4*)(g_wT + q * 256 * KK);
        for (int i = tid; i < (256 * KK) / 4; i += 256) ((float4*)wts)[i] = src[i];
    }
    __syncthreads();

    const float* fmc0 = fm + (size_t)b0 * (CC * HWN) + (size_t)(q * 256 + wid * 32) * HWN;
    const float* fmc1 = fmc0 + (size_t)(CC * HWN);
    const float* wrow = &wts[(wid * 32) * KK];

    ull A0[8], A1[8], B0[8], B1[8];
#pragma unroll
    for (int i = 0; i < 8; i++) { A0[i] = A1[i] = B0[i] = B1[i] = 0ull; }

    // depth-1 ring on fm values (4 loads in flight)
    float u0 = fmc0[lane];
    float u1 = hi ? fmc0[lane + 32] : 0.0f;
    float w0 = fmc1[lane];
    float w1 = hi ? fmc1[lane + 32] : 0.0f;

#pragma unroll 4
    for (int j = 0; j < 32; j++) {
        float nu0, nu1, nw0, nw1;
        if (j < 31) {
            nu0 = fmc0[(j + 1) * HWN + lane];
            nu1 = hi ? fmc0[(j + 1) * HWN + lane + 32] : 0.0f;
            nw0 = fmc1[(j + 1) * HWN + lane];
            nw1 = hi ? fmc1[(j + 1) * HWN + lane + 32] : 0.0f;
        }
        ull vu0 = pack2(u0, u0), vu1 = pack2(u1, u1);
        ull vw0 = pack2(w0, w0), vw1 = pack2(w1, w1);
        const ulonglong2* wp = (const ulonglong2*)(wrow + j * KK);  // uniform LDS.128
        ulonglong2 qA = wp[0], qB = wp[1], qC = wp[2], qD = wp[3];

        A0[0] = ffma2(qA.x, vu0, A0[0]);  A1[0] = ffma2(qA.x, vu1, A1[0]);
        B0[0] = ffma2(qA.x, vw0, B0[0]);  B1[0] = ffma2(qA.x, vw1, B1[0]);
        A0[1] = ffma2(qA.y, vu0, A0[1]);  A1[1] = ffma2(qA.y, vu1, A1[1]);
        B0[1] = ffma2(qA.y, vw0, B0[1]);  B1[1] = ffma2(qA.y, vw1, B1[1]);
        A0[2] = ffma2(qB.x, vu0, A0[2]);  A1[2] = ffma2(qB.x, vu1, A1[2]);
        B0[2] = ffma2(qB.x, vw0, B0[2]);  B1[2] = ffma2(qB.x, vw1, B1[2]);
        A0[3] = ffma2(qB.y, vu0, A0[3]);  A1[3] = ffma2(qB.y, vu1, A1[3]);
        B0[3] = ffma2(qB.y, vw0, B0[3]);  B1[3] = ffma2(qB.y, vw1, B1[3]);
        A0[4] = ffma2(qC.x, vu0, A0[4]);  A1[4] = ffma2(qC.x, vu1, A1[4]);
        B0[4] = ffma2(qC.x, vw0, B0[4]);  B1[4] = ffma2(qC.x, vw1, B1[4]);
        A0[5] = ffma2(qC.y, vu0, A0[5]);  A1[5] = ffma2(qC.y, vu1, A1[5]);
        B0[5] = ffma2(qC.y, vw0, B0[5]);  B1[5] = ffma2(qC.y, vw1, B1[5]);
        A0[6] = ffma2(qD.x, vu0, A0[6]);  A1[6] = ffma2(qD.x, vu1, A1[6]);
        B0[6] = ffma2(qD.x, vw0, B0[6]);  B1[6] = ffma2(qD.x, vw1, B1[6]);
        A0[7] = ffma2(qD.y, vu0, A0[7]);  A1[7] = ffma2(qD.y, vu1, A1[7]);
        B0[7] = ffma2(qD.y, vw0, B0[7]);  B1[7] = ffma2(qD.y, vw1, B1[7]);

        u0 = nu0; u1 = nu1; w0 = nw0; w1 = nw1;
    }

    // ---- reduce pass for b0 ----
#pragma unroll
    for (int kp = 0; kp < 8; kp++) {
        float a, c0;
        unpack2(A0[kp], a, c0);
        red[wid * 784 + (2 * kp) * 49 + lane] = a;
        red[wid * 784 + (2 * kp + 1) * 49 + lane] = c0;
        if (hi) {
            float x, y;
            unpack2(A1[kp], x, y);
            red[wid * 784 + (2 * kp) * 49 + lane + 32] = x;
            red[wid * 784 + (2 * kp + 1) * 49 + lane + 32] = y;
        }
    }
    __syncthreads();
    {
        float* dst = g_part + ((size_t)b0 * 8 + q) * 784;
        for (int o = tid; o < 784; o += 256) {
            float s = 0.0f;
#pragma unroll
            for (int w = 0; w < 8; w++) s += red[w * 784 + o];
            dst[o] = s;
        }
    }
    __syncthreads();

    // ---- reduce pass for b1 ----
#pragma unroll
    for (int kp = 0; kp < 8; kp++) {
        float a, c0;
        unpack2(B0[kp], a, c0);
        red[wid * 784 + (2 * kp) * 49 + lane] = a;
        red[wid * 784 + (2 * kp + 1) * 49 + lane] = c0;
        if (hi) {
            float x, y;
            unpack2(B1[kp], x, y);
            red[wid * 784 + (2 * kp) * 49 + lane + 32] = x;
            red[wid * 784 + (2 * kp + 1) * 49 + lane + 32] = y;
        }
    }
    __syncthreads();
    {
        float* dst = g_part + ((size_t)b1 * 8 + q) * 784;
        for (int o = tid; o < 784; o += 256) {
            float s = 0.0f;
#pragma unroll
            for (int w = 0; w < 8; w++) s += red[w * 784 + o];
            dst[o] = s;
        }
    }
}

// ============================================================================
// K1b: reduce 8 c-slices, apply BN, relayout [k*49+hw] -> [hw*16+k]
// ============================================================================
__global__ __launch_bounds__(784) void k1b_reduce() {
    const int b = blockIdx.x;
    const int o = threadIdx.x;
    const float* src = g_part + (size_t)b * 8 * 784;
    float s = 0.0f;
#pragma unroll
    for (int qq = 0; qq < 8; qq++) s += src[qq * 784 + o];
    int k = o / 49;
    int hw = o - k * 49;
    g_fc16[b * 784 + hw * 16 + k] = s * g_binv[k] + g_boff[k];
}

// ============================================================================
// K2: bilinear. Block = (c-tile 512, b REVERSED), 128 thr, 4 c/thread.
// fm tile (100KB) + fc16 (3KB) staged via cp.async.bulk (TMA engine — zero
// LSU wavefronts). fc quads via uniform LDS.128 (depth-1 prefetch), amortized
// over 4 c = 32 FFMA2 per 16 return-cycles.
// ============================================================================
#define K2_TILE_BYTES (512 * HWN * 4)      // 100352
#define K2_FC_BYTES   (784 * 4)            // 3136
#define K2_SMEM (K2_TILE_BYTES + K2_FC_BYTES + 16)

__global__ __launch_bounds__(128, 2) void k2_bilinear(const float* __restrict__ fm,
                                                      float* __restrict__ out) {
    extern __shared__ __align__(16) float smem[];
    float* fms = smem;                       // [512][49]
    float* fcs = smem + 512 * HWN;           // [hw][16]
    ull* mbar = (ull*)(smem + 512 * HWN + 784);

    const int tid = threadIdx.x;
    const int b = (BB - 1) - blockIdx.y;     // reverse-b: ride K1's L2 tail
    const int cbase = blockIdx.x * 512;

    uint32_t mbar_a = smem_u32(mbar);
    if (tid == 0) {
        asm volatile("mbarrier.init.shared.b64 [%0], %1;" :: "r"(mbar_a), "r"(1));
    }
    __syncthreads();
    if (tid == 0) {
        asm volatile("mbarrier.arrive.expect_tx.shared.b64 _, [%0], %1;"
                     :: "r"(mbar_a), "r"((uint32_t)(K2_TILE_BYTES + K2_FC_BYTES)));
        const float* src = fm + (size_t)b * (CC * HWN) + (size_t)cbase * HWN;
        asm volatile(
            "cp.async.bulk.shared::cta.global.mbarrier::complete_tx::bytes [%0], [%1], %2, [%3];"
            :: "r"(smem_u32(fms)), "l"(src), "r"((uint32_t)K2_TILE_BYTES), "r"(mbar_a)
            : "memory");
        const float* fsrc = g_fc16 + (size_t)b * 784;
        asm volatile(
            "cp.async.bulk.shared::cta.global.mbarrier::complete_tx::bytes [%0], [%1], %2, [%3];"
            :: "r"(smem_u32(fcs)), "l"(fsrc), "r"((uint32_t)K2_FC_BYTES), "r"(mbar_a)
            : "memory");
    }
    // wait phase 0
    {
        uint32_t done;
        asm volatile(
            "{\n\t.reg .pred p;\n\t"
            "mbarrier.try_wait.parity.acquire.cta.shared::cta.b64 p, [%1], 0;\n\t"
            "selp.b32 %0, 1, 0, p;\n\t}"
            : "=r"(done) : "r"(mbar_a) : "memory");
        if (!done) {
            asm volatile(
                "{\n\t.reg .pred P1;\n\t"
                "W%=:\n\t"
                "mbarrier.try_wait.parity.acquire.cta.shared::cta.b64 P1, [%0], 0, 0x989680;\n\t"
                "@P1 bra.uni D%=;\n\t"
                "bra.uni W%=;\n\t"
                "D%=:\n\t}"
                :: "r"(mbar_a) : "memory");
        }
    }

    const float* r0 = &fms[tid * HWN];
    const float* r1 = &fms[(tid + 128) * HWN];
    const float* r2 = &fms[(tid + 256) * HWN];
    const float* r3 = &fms[(tid + 384) * HWN];
    const ulonglong2* fq = (const ulonglong2*)fcs;

    ull acc[4][8];
#pragma unroll
    for (int i = 0; i < 4; i++)
#pragma unroll
        for (int j = 0; j < 8; j++) acc[i][j] = 0ull;

    ulonglong2 q0 = fq[0], q1 = fq[1], q2 = fq[2], q3 = fq[3];

#pragma unroll 7
    for (int hw = 0; hw < HWN; hw++) {
        ulonglong2 n0, n1, n2, n3;
        if (hw < HWN - 1) {
            n0 = fq[(hw + 1) * 4 + 0];
            n1 = fq[(hw + 1) * 4 + 1];
            n2 = fq[(hw + 1) * 4 + 2];
            n3 = fq[(hw + 1) * 4 + 3];
        }
        float va = r0[hw], vb = r1[hw], vc = r2[hw], vd = r3[hw];
        ull vva = pack2(va, va), vvb = pack2(vb, vb);
        ull vvc = pack2(vc, vc), vvd = pack2(vd, vd);

        acc[0][0] = ffma2(q0.x, vva, acc[0][0]);  acc[1][0] = ffma2(q0.x, vvb, acc[1][0]);
        acc[2][0] = ffma2(q0.x, vvc, acc[2][0]);  acc[3][0] = ffma2(q0.x, vvd, acc[3][0]);
        acc[0][1] = ffma2(q0.y, vva, acc[0][1]);  acc[1][1] = ffma2(q0.y, vvb, acc[1][1]);
        acc[2][1] = ffma2(q0.y, vvc, acc[2][1]);  acc[3][1] = ffma2(q0.y, vvd, acc[3][1]);
        acc[0][2] = ffma2(q1.x, vva, acc[0][2]);  acc[1][2] = ffma2(q1.x, vvb, acc[1][2]);
        acc[2][2] = ffma2(q1.x, vvc, acc[2][2]);  acc[3][2] = ffma2(q1.x, vvd, acc[3][2]);
        acc[0][3] = ffma2(q1.y, vva, acc[0][3]);  acc[1][3] = ffma2(q1.y, vvb, acc[1][3]);
        acc[2][3] = ffma2(q1.y, vvc, acc[2][3]);  acc[3][3] = ffma2(q1.y, vvd, acc[3][3]);
        acc[0][4] = ffma2(q2.x, vva, acc[0][4]);  acc[1][4] = ffma2(q2.x, vvb, acc[1][4]);
        acc[2][4] = ffma2(q2.x, vvc, acc[2][4]);  acc[3][4] = ffma2(q2.x, vvd, acc[3][4]);
        acc[0][5] = ffma2(q2.y, vva, acc[0][5]);  acc[1][5] = ffma2(q2.y, vvb, acc[1][5]);
        acc[2][5] = ffma2(q2.y, vvc, acc[2][5]);  acc[3][5] = ffma2(q2.y, vvd, acc[3][5]);
        acc[0][6] = ffma2(q3.x, vva, acc[0][6]);  acc[1][6] = ffma2(q3.x, vvb, acc[1][6]);
        acc[2][6] = ffma2(q3.x, vvc, acc[2][6]);  acc[3][6] = ffma2(q3.x, vvd, acc[3][6]);
        acc[0][7] = ffma2(q3.y, vva, acc[0][7]);  acc[1][7] = ffma2(q3.y, vvb, acc[1][7]);
        acc[2][7] = ffma2(q3.y, vvc, acc[2][7]);  acc[3][7] = ffma2(q3.y, vvd, acc[3][7]);

        q0 = n0; q1 = n1; q2 = n2; q3 = n3;
    }

#pragma unroll
    for (int i = 0; i < 4; i++) {
        float* ob = out + (size_t)b * 32768 + cbase + i * 128 + tid;
#pragma unroll
        for (int kp = 0; kp < 8; kp++) {
            float x, y;
            unpack2(acc[i][kp], x, y);
            ob[(2 * kp) * 2048] = x;
            ob[(2 * kp + 1) * 2048] = y;
        }
    }
}

extern "C" void kernel_launch(void* const* d_in, const int* in_sizes, int n_in,
                              void* d_out, int out_size) {
    const float* fm  = (const float*)d_in[0];  // [256,2048,7,7]
    const float* w16 = (const float*)d_in[1];  // [16,2048]
    const float* bng = (const float*)d_in[2];
    const float* bnb = (const float*)d_in[3];
    const float* bnm = (const float*)d_in[4];
    const float* bnv = (const float*)d_in[5];
    float* out = (float*)d_out;

    cudaFuncSetAttribute(k2_bilinear, cudaFuncAttributeMaxDynamicSharedMemorySize,
                         K2_SMEM);

    k0_prep<<<(CC * KK + 255) / 256, 256>>>(w16, bng, bnb, bnm, bnv);
    dim3 g1(8, BB / 2);   // 1024 blocks: (q-slice, b-pair)
    k1_conv<<<g1, 256>>>(fm);
    k1b_reduce<<<BB, 784>>>();
    dim3 g2(4, BB);       // 1024 blocks: (c-tile of 512, b)
    k2_bilinear<<<g2, 128, K2_SMEM>>>(fm, out);
}